// round 1
// baseline (speedup 1.0000x reference)
#include <cuda_runtime.h>
#include <cuda_fp16.h>

#define DIM       33
#define BINS      32
#define NTHREADS  512
#define NGROUPS   49
#define NCHUNKS   8192            // (4*2048*2048/4) / NTHREADS
#define PLANE4    1048576         // 2048*2048/4
#define NPAIR     (DIM*DIM*BINS)  // 34848 half2 pairs per channel
#define SMEM_BYTES (NPAIR * 4)    // 139392 B

// Persistent channel-split trilinear LUT kernel.
// CTA b: channel = b%3, pixel group = b/3 (49 groups). Each CTA builds an
// fp16 overlapping-pair LUT in smem: P[(b0*33+g0)*32 + r0] = (L[r0], L[r0+1]),
// so every corner pair is ONE aligned 4-byte LDS (4 LDS.32 per pixel).
__global__ __launch_bounds__(NTHREADS, 1)
void lut3d_kernel(const float* __restrict__ x, const float* __restrict__ lut,
                  float* __restrict__ out) {
    extern __shared__ __half2 sP[];
    const int ch  = blockIdx.x % 3;
    const int grp = blockIdx.x / 3;

    // Build smem pair table for this channel (coalesced reads of the 143.7KB slab).
    const float* lc = lut + ch * (DIM * DIM * DIM);
    for (int i = threadIdx.x; i < NPAIR; i += NTHREADS) {
        int r0 = i & (BINS - 1);
        int j  = i >> 5;            // combined (b0*33 + g0)
        float v0 = lc[j * DIM + r0];
        float v1 = lc[j * DIM + r0 + 1];
        sP[i] = __floats2half2_rn(v0, v1);
    }
    __syncthreads();

    const float4* __restrict__ X = reinterpret_cast<const float4*>(x);
    float4* __restrict__ O       = reinterpret_cast<float4*>(out);

    int c = grp;
    int v = c * NTHREADS + threadIdx.x;
    int batch = v >> 20;                 // PLANE4 = 2^20
    int off   = v & (PLANE4 - 1);
    int base  = batch * 3 * PLANE4 + off;
    float4 R  = X[base];
    float4 G  = X[base + PLANE4];
    float4 Bv = X[base + 2 * PLANE4];

    while (true) {
        // Software prefetch of the next chunk (hides ~600cyc HBM latency at 16 warps).
        int cn = c + NGROUPS;
        bool more = (cn < NCHUNKS);
        int basen = 0;
        float4 Rn, Gn, Bn;
        if (more) {
            int vn = cn * NTHREADS + threadIdx.x;
            int bn = vn >> 20;
            int on = vn & (PLANE4 - 1);
            basen = bn * 3 * PLANE4 + on;
            Rn = X[basen];
            Gn = X[basen + PLANE4];
            Bn = X[basen + 2 * PLANE4];
        }

        float rp[4] = {R.x, R.y, R.z, R.w};
        float gp[4] = {G.x, G.y, G.z, G.w};
        float bp[4] = {Bv.x, Bv.y, Bv.z, Bv.w};
        float o[4];
        #pragma unroll
        for (int k = 0; k < 4; k++) {
            float rr = rp[k] * (float)BINS;
            float gg = gp[k] * (float)BINS;
            float bb = bp[k] * (float)BINS;
            int r0 = min(__float2int_rd(rr), BINS - 1);
            int g0 = min(__float2int_rd(gg), BINS - 1);
            int b0 = min(__float2int_rd(bb), BINS - 1);
            float fr = rr - (float)r0;
            float fg = gg - (float)g0;
            float fb = bb - (float)b0;
            int idx = (b0 * DIM + g0) * BINS + r0;
            // 4 corner pairs = 4 aligned LDS.32 (immediate offsets)
            float2 v00 = __half22float2(sP[idx]);
            float2 v01 = __half22float2(sP[idx + BINS]);            // g0+1
            float2 v10 = __half22float2(sP[idx + DIM * BINS]);      // b0+1
            float2 v11 = __half22float2(sP[idx + DIM * BINS + BINS]);
            // factored trilinear: 4 r-lerps, 2 g-lerps, 1 b-lerp
            float c00 = fmaf(fr, v00.y - v00.x, v00.x);
            float c01 = fmaf(fr, v01.y - v01.x, v01.x);
            float c10 = fmaf(fr, v10.y - v10.x, v10.x);
            float c11 = fmaf(fr, v11.y - v11.x, v11.x);
            float c0  = fmaf(fg, c01 - c00, c00);
            float c1  = fmaf(fg, c11 - c10, c10);
            o[k] = fmaf(fb, c1 - c0, c0);
        }
        O[base + ch * PLANE4] = make_float4(o[0], o[1], o[2], o[3]);

        if (!more) break;
        c = cn; base = basen; R = Rn; G = Gn; Bv = Bn;
    }
}

extern "C" void kernel_launch(void* const* d_in, const int* in_sizes, int n_in,
                              void* d_out, int out_size) {
    const float* x   = (const float*)d_in[0];
    const float* lut = (const float*)d_in[1];
    // x has 50,331,648 elems; LUT has 107,811. Swap defensively if order differs.
    if (n_in >= 2 && in_sizes[0] < in_sizes[1]) {
        x   = (const float*)d_in[1];
        lut = (const float*)d_in[0];
    }
    cudaFuncSetAttribute((const void*)lut3d_kernel,
                         cudaFuncAttributeMaxDynamicSharedMemorySize, SMEM_BYTES);
    lut3d_kernel<<<3 * NGROUPS, NTHREADS, SMEM_BYTES>>>(x, lut, (float*)d_out);
}

// round 2
// speedup vs baseline: 1.3215x; 1.3215x over previous
#include <cuda_runtime.h>
#include <cuda_fp16.h>

#define DIM       33
#define BINS      32
#define NTHREADS  1024
#define NGROUPS   49
#define NCHUNKS   4096            // (4*2048*2048/4) / NTHREADS
#define PLANE4    1048576         // 2048*2048/4
#define NPAIR     (DIM*DIM*BINS)  // 34848 half2 pairs per channel
#define SMEM_BYTES (NPAIR * 4)    // 139392 B

// Persistent channel-split trilinear LUT kernel.
// CTA b: channel = b%3, pixel group = b/3 (49 groups). Each CTA builds an
// fp16 overlapping-pair LUT in smem: P[(b0*33+g0)*32 + r0] = (L[r0], L[r0+1]),
// so every corner pair is ONE aligned 4-byte LDS (4 LDS.32 per pixel).
// 1024 threads/CTA -> 32 warps/SM to saturate the shared crossbar.
__global__ __launch_bounds__(NTHREADS, 1)
void lut3d_kernel(const float* __restrict__ x, const float* __restrict__ lut,
                  float* __restrict__ out) {
    extern __shared__ __half2 sP[];
    const int ch  = blockIdx.x % 3;
    const int grp = blockIdx.x / 3;

    // Build smem pair table for this channel (coalesced reads of the 139KB slab).
    const float* lc = lut + ch * (DIM * DIM * DIM);
    for (int i = threadIdx.x; i < NPAIR; i += NTHREADS) {
        int r0 = i & (BINS - 1);
        int j  = i >> 5;            // combined (b0*33 + g0)
        float v0 = lc[j * DIM + r0];
        float v1 = lc[j * DIM + r0 + 1];
        sP[i] = __floats2half2_rn(v0, v1);
    }
    __syncthreads();

    const float4* __restrict__ X = reinterpret_cast<const float4*>(x);
    float4* __restrict__ O       = reinterpret_cast<float4*>(out);

    int c = grp;
    int v = c * NTHREADS + threadIdx.x;
    int batch = v >> 20;                 // PLANE4 = 2^20
    int off   = v & (PLANE4 - 1);
    int base  = batch * 3 * PLANE4 + off;
    float4 R  = X[base];
    float4 G  = X[base + PLANE4];
    float4 Bv = X[base + 2 * PLANE4];

    while (true) {
        // Software prefetch of the next chunk (overlaps HBM latency with LDS work).
        int cn = c + NGROUPS;
        bool more = (cn < NCHUNKS);
        int basen = 0;
        float4 Rn, Gn, Bn;
        if (more) {
            int vn = cn * NTHREADS + threadIdx.x;
            int bn = vn >> 20;
            int on = vn & (PLANE4 - 1);
            basen = bn * 3 * PLANE4 + on;
            Rn = X[basen];
            Gn = X[basen + PLANE4];
            Bn = X[basen + 2 * PLANE4];
        }

        float rp[4] = {R.x, R.y, R.z, R.w};
        float gp[4] = {G.x, G.y, G.z, G.w};
        float bp[4] = {Bv.x, Bv.y, Bv.z, Bv.w};
        float o[4];
        #pragma unroll
        for (int k = 0; k < 4; k++) {
            float rr = rp[k] * (float)BINS;
            float gg = gp[k] * (float)BINS;
            float bb = bp[k] * (float)BINS;
            int r0 = min(__float2int_rd(rr), BINS - 1);
            int g0 = min(__float2int_rd(gg), BINS - 1);
            int b0 = min(__float2int_rd(bb), BINS - 1);
            float fr = rr - (float)r0;
            float fg = gg - (float)g0;
            float fb = bb - (float)b0;
            int idx = (b0 * DIM + g0) * BINS + r0;
            // 4 corner pairs = 4 aligned LDS.32 (immediate offsets)
            float2 v00 = __half22float2(sP[idx]);
            float2 v01 = __half22float2(sP[idx + BINS]);            // g0+1
            float2 v10 = __half22float2(sP[idx + DIM * BINS]);      // b0+1
            float2 v11 = __half22float2(sP[idx + DIM * BINS + BINS]);
            // factored trilinear: 4 r-lerps, 2 g-lerps, 1 b-lerp
            float c00 = fmaf(fr, v00.y - v00.x, v00.x);
            float c01 = fmaf(fr, v01.y - v01.x, v01.x);
            float c10 = fmaf(fr, v10.y - v10.x, v10.x);
            float c11 = fmaf(fr, v11.y - v11.x, v11.x);
            float c0  = fmaf(fg, c01 - c00, c00);
            float c1  = fmaf(fg, c11 - c10, c10);
            o[k] = fmaf(fb, c1 - c0, c0);
        }
        O[base + ch * PLANE4] = make_float4(o[0], o[1], o[2], o[3]);

        if (!more) break;
        c = cn; base = basen; R = Rn; G = Gn; Bv = Bn;
    }
}

extern "C" void kernel_launch(void* const* d_in, const int* in_sizes, int n_in,
                              void* d_out, int out_size) {
    const float* x   = (const float*)d_in[0];
    const float* lut = (const float*)d_in[1];
    // x has 50,331,648 elems; LUT has 107,811. Swap defensively if order differs.
    if (n_in >= 2 && in_sizes[0] < in_sizes[1]) {
        x   = (const float*)d_in[1];
        lut = (const float*)d_in[0];
    }
    cudaFuncSetAttribute((const void*)lut3d_kernel,
                         cudaFuncAttributeMaxDynamicSharedMemorySize, SMEM_BYTES);
    lut3d_kernel<<<3 * NGROUPS, NTHREADS, SMEM_BYTES>>>(x, lut, (float*)d_out);
}